// round 7
// baseline (speedup 1.0000x reference)
#include <cuda_runtime.h>

// JointIntegralRegressor: soft-argmax over [16,24,64,64,64] fp32 heatmaps.
// Single kernel, cluster-fused: each slice = one 8-CTA cluster. Chunk CTAs
// push their partial moments into rank0's SMEM (st.shared::cluster) and
// arrive on rank0's mbarrier (release, CLUSTER scope — no gpu-scope membar,
// which cost +10us in earlier fused attempts). Rank0 acquires, combines in
// fixed rank order (deterministic), writes the 3 coords. No second kernel.

#define DIM_W 64
#define DIM_H 64
#define DIM_D 64
#define SLICES 384                           // 16*24
#define SLICE_ELEMS (DIM_D * DIM_H * DIM_W)  // 262144
#define CHUNKS_PER_SLICE 8
#define CHUNK_ELEMS (SLICE_ELEMS / CHUNKS_PER_SLICE)   // 32768
#define NCHUNKS (SLICES * CHUNKS_PER_SLICE)            // 3072
#define P1_THREADS 256
#define V4_PER_THREAD (CHUNK_ELEMS / 4 / P1_THREADS)   // 32

__device__ __forceinline__ unsigned smem_u32(const void* p) {
    unsigned a;
    asm("{ .reg .u64 t; cvta.to.shared.u64 t, %1; cvt.u32.u64 %0, t; }"
        : "=r"(a) : "l"(p));
    return a;
}

__global__ __launch_bounds__(P1_THREADS) __cluster_dims__(CHUNKS_PER_SLICE, 1, 1)
void jir_fused(const float* __restrict__ in, float* __restrict__ out) {
    __shared__ float4 red[P1_THREADS / 32];
    __shared__ float4 slots[CHUNKS_PER_SLICE];          // rank0's inbox
    __shared__ alignas(8) unsigned long long mbar;

    const int chunk = blockIdx.x;
    const int tid = threadIdx.x;
    unsigned rank;
    asm("mov.u32 %0, %%cluster_ctarank;" : "=r"(rank));

    const unsigned mbar_a = smem_u32(&mbar);

    // Init rank0's mbarrier (count = 8 arrivals), publish to cluster.
    if (rank == 0 && tid == 0) {
        asm volatile("mbarrier.init.shared.b64 [%0], %1;"
                     :: "r"(mbar_a), "r"((unsigned)CHUNKS_PER_SLICE) : "memory");
        asm volatile("fence.mbarrier_init.release.cluster;" ::: "memory");
    }
    asm volatile("barrier.cluster.arrive.aligned;" ::: "memory");
    asm volatile("barrier.cluster.wait.aligned;" ::: "memory");

    // ---- streaming mainloop (identical to best-known pass1) ----
    const float4* __restrict__ in4 =
        reinterpret_cast<const float4*>(in) + (long long)chunk * (CHUNK_ELEMS / 4);
    const int elem0 = (chunk & (CHUNKS_PER_SLICE - 1)) * CHUNK_ELEMS;

    float s = 0.f, sx = 0.f, sy = 0.f, sz = 0.f;

    #pragma unroll 4
    for (int it = 0; it < V4_PER_THREAD; ++it) {
        const int idx4 = it * P1_THREADS + tid;
        const float4 v = __ldcs(&in4[idx4]);        // read-once: evict-first

        const int e  = elem0 + idx4 * 4;
        const float w0 = (float)(e & (DIM_W - 1));
        const int   hd = e >> 6;
        const float hf = (float)(hd & (DIM_H - 1));
        const float df = (float)(hd >> 6);

        const float e0 = __expf(v.x);
        const float e1 = __expf(v.y);
        const float e2 = __expf(v.z);
        const float e3 = __expf(v.w);

        const float sp = (e0 + e1) + (e2 + e3);
        float inner = fmaf(2.f, e2, e1);
        inner       = fmaf(3.f, e3, inner);

        s  += sp;
        sx += fmaf(w0, sp, inner);
        sy  = fmaf(hf, sp, sy);
        sz  = fmaf(df, sp, sz);
    }

    // Block reduction.
    #pragma unroll
    for (int off = 16; off > 0; off >>= 1) {
        s  += __shfl_down_sync(0xFFFFFFFFu, s,  off);
        sx += __shfl_down_sync(0xFFFFFFFFu, sx, off);
        sy += __shfl_down_sync(0xFFFFFFFFu, sy, off);
        sz += __shfl_down_sync(0xFFFFFFFFu, sz, off);
    }
    const int warp = tid >> 5;
    const int lane = tid & 31;
    if (lane == 0) red[warp] = make_float4(s, sx, sy, sz);
    __syncthreads();

    if (tid == 0) {
        float4 acc = red[0];
        #pragma unroll
        for (int i = 1; i < P1_THREADS / 32; ++i) {
            acc.x += red[i].x;
            acc.y += red[i].y;
            acc.z += red[i].z;
            acc.w += red[i].w;
        }

        // Push partial into rank0's slots[rank] (cluster-scope remote store).
        const unsigned slot_local = smem_u32(&slots[rank]);
        unsigned slot_r0;
        asm volatile("mapa.shared::cluster.u32 %0, %1, 0;"
                     : "=r"(slot_r0) : "r"(slot_local));
        asm volatile("st.shared::cluster.f32 [%0+0],  %1;" :: "r"(slot_r0), "f"(acc.x) : "memory");
        asm volatile("st.shared::cluster.f32 [%0+4],  %1;" :: "r"(slot_r0), "f"(acc.y) : "memory");
        asm volatile("st.shared::cluster.f32 [%0+8],  %1;" :: "r"(slot_r0), "f"(acc.z) : "memory");
        asm volatile("st.shared::cluster.f32 [%0+12], %1;" :: "r"(slot_r0), "f"(acc.w) : "memory");

        // Release-arrive on rank0's mbarrier (cluster scope only).
        unsigned mbar_r0;
        asm volatile("mapa.shared::cluster.u32 %0, %1, 0;"
                     : "=r"(mbar_r0) : "r"(mbar_a));
        asm volatile("mbarrier.arrive.release.cluster.shared::cluster.b64 _, [%0];"
                     :: "r"(mbar_r0) : "memory");

        if (rank == 0) {
            // Acquire-wait for all 8 arrivals (phase 0 completes).
            asm volatile(
                "{\n\t.reg .pred P1;\n\t"
                "WAIT_%=:\n\t"
                "mbarrier.try_wait.parity.acquire.cluster.shared::cta.b64 P1, [%0], 0;\n\t"
                "@P1 bra DONE_%=;\n\t"
                "bra WAIT_%=;\n\t"
                "DONE_%=:\n\t}"
                :: "r"(mbar_a) : "memory");

            float fs = 0.f, fsx = 0.f, fsy = 0.f, fsz = 0.f;
            #pragma unroll
            for (int c = 0; c < CHUNKS_PER_SLICE; ++c) {
                const float4 p = slots[c];
                fs += p.x; fsx += p.y; fsy += p.z; fsz += p.w;
            }
            const float inv = 1.0f / fs;
            const float scale = 1.0f / 64.0f;
            const int slice = chunk >> 3;
            out[slice * 3 + 0] = fsx * inv * scale - 0.5f;
            out[slice * 3 + 1] = fsy * inv * scale - 0.5f;
            out[slice * 3 + 2] = fsz * inv * scale - 0.5f;
        }
    }
}

extern "C" void kernel_launch(void* const* d_in, const int* in_sizes, int n_in,
                              void* d_out, int out_size) {
    const float* heatmaps = (const float*)d_in[0];
    float* out = (float*)d_out;
    jir_fused<<<NCHUNKS, P1_THREADS>>>(heatmaps, out);
}

// round 9
// speedup vs baseline: 1.0985x; 1.0985x over previous
#include <cuda_runtime.h>

// JointIntegralRegressor: soft-argmax over [16,24,64,64,64] fp32 heatmaps.
// SINGLE launch: 3072 producer CTAs (bit-identical streaming mainloop,
// epilogue = st.cg partial + fire-and-forget red.release counter bump) +
// 384 combiner CTAs appended at the grid tail. Combiners spin (acquire +
// nanosleep) until their slice's 8 partials land, combine in fixed order
// (deterministic), write 3 floats, reset the counter for the next replay.
// Producers never wait on combiners -> no deadlock; combiner footprint tiny.

#define DIM_W 64
#define DIM_H 64
#define DIM_D 64
#define SLICES 384                           // 16*24
#define SLICE_ELEMS (DIM_D * DIM_H * DIM_W)  // 262144
#define CHUNKS_PER_SLICE 8
#define CHUNK_ELEMS (SLICE_ELEMS / CHUNKS_PER_SLICE)   // 32768
#define NCHUNKS (SLICES * CHUNKS_PER_SLICE)            // 3072
#define P1_THREADS 256
#define V4_PER_THREAD (CHUNK_ELEMS / 4 / P1_THREADS)   // 32

__device__ float4 g_partials[NCHUNKS];
__device__ unsigned int g_cnt[SLICES];       // zero-init; combiner self-resets

__global__ __launch_bounds__(P1_THREADS)
void jir_single(const float* __restrict__ in, float* __restrict__ out) {
    const int bid = blockIdx.x;
    const int tid = threadIdx.x;

    if (bid < NCHUNKS) {
        // ---------------- producer ----------------
        const int chunk = bid;
        const int slice = chunk >> 3;

        const float4* __restrict__ in4 =
            reinterpret_cast<const float4*>(in) + (long long)chunk * (CHUNK_ELEMS / 4);
        const int elem0 = (chunk & (CHUNKS_PER_SLICE - 1)) * CHUNK_ELEMS;

        float s = 0.f, sx = 0.f, sy = 0.f, sz = 0.f;

        #pragma unroll 4
        for (int it = 0; it < V4_PER_THREAD; ++it) {
            const int idx4 = it * P1_THREADS + tid;
            const float4 v = __ldcs(&in4[idx4]);        // read-once: evict-first

            const int e  = elem0 + idx4 * 4;
            const float w0 = (float)(e & (DIM_W - 1));
            const int   hd = e >> 6;
            const float hf = (float)(hd & (DIM_H - 1));
            const float df = (float)(hd >> 6);

            const float e0 = __expf(v.x);
            const float e1 = __expf(v.y);
            const float e2 = __expf(v.z);
            const float e3 = __expf(v.w);

            const float sp = (e0 + e1) + (e2 + e3);
            float inner = fmaf(2.f, e2, e1);
            inner       = fmaf(3.f, e3, inner);

            s  += sp;
            sx += fmaf(w0, sp, inner);
            sy  = fmaf(hf, sp, sy);
            sz  = fmaf(df, sp, sz);
        }

        #pragma unroll
        for (int off = 16; off > 0; off >>= 1) {
            s  += __shfl_down_sync(0xFFFFFFFFu, s,  off);
            sx += __shfl_down_sync(0xFFFFFFFFu, sx, off);
            sy += __shfl_down_sync(0xFFFFFFFFu, sy, off);
            sz += __shfl_down_sync(0xFFFFFFFFu, sz, off);
        }

        __shared__ float4 red[P1_THREADS / 32];
        const int warp = tid >> 5;
        const int lane = tid & 31;
        if (lane == 0) red[warp] = make_float4(s, sx, sy, sz);
        __syncthreads();

        if (tid == 0) {
            float4 acc = red[0];
            #pragma unroll
            for (int i = 1; i < P1_THREADS / 32; ++i) {
                acc.x += red[i].x;
                acc.y += red[i].y;
                acc.z += red[i].z;
                acc.w += red[i].w;
            }
            // Publish partial (L2), then fire-and-forget release bump.
            asm volatile("st.global.cg.v4.f32 [%0], {%1, %2, %3, %4};"
                         :: "l"(&g_partials[chunk]),
                            "f"(acc.x), "f"(acc.y), "f"(acc.z), "f"(acc.w)
                         : "memory");
            asm volatile("red.release.gpu.global.add.u32 [%0], %1;"
                         :: "l"(&g_cnt[slice]), "r"(1u) : "memory");
        }
    } else {
        // ---------------- combiner (one active warp) ----------------
        const int slice = bid - NCHUNKS;
        if (tid >= 32) return;
        const int lane = tid;

        if (lane == 0) {
            unsigned int c;
            for (;;) {
                asm volatile("ld.acquire.gpu.global.u32 %0, [%1];"
                             : "=r"(c) : "l"(&g_cnt[slice]) : "memory");
                if (c >= CHUNKS_PER_SLICE) break;
                __nanosleep(64);
            }
        }
        __syncwarp();

        float s = 0.f, sx = 0.f, sy = 0.f, sz = 0.f;
        if (lane < CHUNKS_PER_SLICE) {
            float px, py, pz, pw;
            asm volatile("ld.global.cg.v4.f32 {%0, %1, %2, %3}, [%4];"
                         : "=f"(px), "=f"(py), "=f"(pz), "=f"(pw)
                         : "l"(&g_partials[slice * CHUNKS_PER_SLICE + lane])
                         : "memory");
            s = px; sx = py; sy = pz; sz = pw;
        }

        #pragma unroll
        for (int off = 4; off > 0; off >>= 1) {
            s  += __shfl_down_sync(0xFFFFFFFFu, s,  off);
            sx += __shfl_down_sync(0xFFFFFFFFu, sx, off);
            sy += __shfl_down_sync(0xFFFFFFFFu, sy, off);
            sz += __shfl_down_sync(0xFFFFFFFFu, sz, off);
        }

        if (lane == 0) {
            const float inv = 1.0f / s;
            const float scale = 1.0f / 64.0f;
            out[slice * 3 + 0] = sx * inv * scale - 0.5f;
            out[slice * 3 + 1] = sy * inv * scale - 0.5f;
            out[slice * 3 + 2] = sz * inv * scale - 0.5f;
            // Reset for next graph replay (same L2 path as the red target).
            asm volatile("st.global.cg.u32 [%0], %1;"
                         :: "l"(&g_cnt[slice]), "r"(0u) : "memory");
        }
    }
}

extern "C" void kernel_launch(void* const* d_in, const int* in_sizes, int n_in,
                              void* d_out, int out_size) {
    const float* heatmaps = (const float*)d_in[0];
    float* out = (float*)d_out;
    jir_single<<<NCHUNKS + SLICES, P1_THREADS>>>(heatmaps, out);
}